// round 11
// baseline (speedup 1.0000x reference)
#include <cuda_runtime.h>
#include <cstdint>

// PatchEmbedding: x(1,3,384,384) f32, W(768,12), b(768), positions(768,146689)
// out[e,l] = b[e] + positions[e,l] + sum_d patch[d,l] * W[e,d]
//
// W/b in __constant__ (uniform const path). pos streamed into smem by a
// DEDICATED PRODUCER WARP issuing cp.async.bulk rows into a 4-deep mbarrier
// ring; 8 consumer warps never issue a long-latency load.

#define IMG      384
#define LW       383
#define L_TOTAL  146689              // 383*383
#define EMB      768
#define PD       12

#define CTPB     256                 // compute threads (8 warps)
#define TPB      288                 // + 1 producer warp
#define E_TILE   64                  // 768/64 = 12 y-blocks
#define CH       8                   // e-rows per stage
#define NCH      (E_TILE / CH)       // 8 stages of work
#define NSTAGE   4                   // ring depth (slots reused twice)

// Row copy: 260 floats (1040B, 16B-multiple) starting at src - (e&3) floats
// so the bulk source is 16B-aligned (L odd => row starts rotate mod 4).
#define ROWF     260
#define ROWB     (ROWF * 4)          // 1040
#define STAGEF   (CH * ROWF)         // 2080 floats
#define STAGEB   (CH * ROWB)         // 8320 bytes

__constant__ float4 cW4[EMB * 3];
__constant__ float  cB[EMB];

__device__ __forceinline__ void gather_patch(const float* __restrict__ x,
                                             int l, float* p) {
    const int r   = l / LW;
    const int col = l - r * LW;
    const float* xp = x + r * IMG + col;
    #pragma unroll
    for (int c = 0; c < 3; c++)
        #pragma unroll
        for (int i = 0; i < 2; i++)
            #pragma unroll
            for (int j = 0; j < 2; j++)
                p[c * 4 + i * 2 + j] = xp[c * IMG * IMG + i * IMG + j];
}

__device__ __forceinline__ void mbar_init(uint32_t bar, uint32_t cnt) {
    asm volatile("mbarrier.init.shared.b64 [%0], %1;" :: "r"(bar), "r"(cnt) : "memory");
}
__device__ __forceinline__ void mbar_expect_tx(uint32_t bar, uint32_t bytes) {
    asm volatile("mbarrier.arrive.expect_tx.shared.b64 _, [%0], %1;"
                 :: "r"(bar), "r"(bytes) : "memory");
}
__device__ __forceinline__ void mbar_arrive(uint32_t bar) {
    asm volatile("mbarrier.arrive.shared.b64 _, [%0];" :: "r"(bar) : "memory");
}
__device__ __forceinline__ void mbar_wait(uint32_t bar, uint32_t parity) {
    asm volatile(
        "{\n\t.reg .pred P;\n\t"
        "W%=:\n\t"
        "mbarrier.try_wait.parity.shared.b64 P, [%0], %1, 0x989680;\n\t"
        "@P bra.uni D%=;\n\t"
        "bra.uni W%=;\n\t"
        "D%=:\n\t}"
        :: "r"(bar), "r"(parity) : "memory");
}
__device__ __forceinline__ void bulk_cp(uint32_t dst, const float* src,
                                        uint32_t bar) {
    asm volatile(
        "cp.async.bulk.shared::cta.global.mbarrier::complete_tx::bytes "
        "[%0], [%1], %2, [%3];"
        :: "r"(dst), "l"(src), "r"((uint32_t)ROWB), "r"(bar) : "memory");
}

__global__ __launch_bounds__(TPB, 5)
void patch_embed_kernel(const float* __restrict__ x,
                        const float* __restrict__ pos,
                        float* __restrict__ out) {
    __shared__ __align__(16) float spv[NSTAGE * STAGEF];   // 33,280 B
    __shared__ __align__(8)  unsigned long long mbar[2 * NSTAGE];

    const int e0 = blockIdx.y * E_TILE;
    const int l0 = blockIdx.x * CTPB;

    if (blockIdx.x == gridDim.x - 1) {
        // ---- tail x-block: 146688..: 1 valid l; scalar path ----
        const int l = l0 + threadIdx.x;
        if (l < L_TOTAL) {
            float p[PD];
            gather_patch(x, l, p);
            for (int ee = 0; ee < E_TILE; ee++) {
                const int e = e0 + ee;
                const float4 w0 = cW4[e * 3 + 0];
                const float4 w1 = cW4[e * 3 + 1];
                const float4 w2 = cW4[e * 3 + 2];
                float c0 = fmaf(p[0], w0.x, cB[e]);
                float c1 = p[1] * w0.y;
                c0 = fmaf(p[2],  w0.z, c0);  c1 = fmaf(p[3],  w0.w, c1);
                c0 = fmaf(p[4],  w1.x, c0);  c1 = fmaf(p[5],  w1.y, c1);
                c0 = fmaf(p[6],  w1.z, c0);  c1 = fmaf(p[7],  w1.w, c1);
                c0 = fmaf(p[8],  w2.x, c0);  c1 = fmaf(p[9],  w2.y, c1);
                c0 = fmaf(p[10], w2.z, c0);  c1 = fmaf(p[11], w2.w, c1);
                const float pvv = pos[(size_t)e * L_TOTAL + l];
                out[(size_t)e * L_TOTAL + l] = (c0 + c1) + pvv;
            }
        }
        return;
    }

    // ---- full blocks ----
    const uint32_t sbase = (uint32_t)__cvta_generic_to_shared(spv);
    const uint32_t bbase = (uint32_t)__cvta_generic_to_shared(mbar);
    #define FULLB(s)  (bbase + (uint32_t)(s) * 8u)
    #define EMPTYB(s) (bbase + (uint32_t)(NSTAGE + (s)) * 8u)

    if (threadIdx.x == 0) {
        #pragma unroll
        for (int s = 0; s < NSTAGE; s++) {
            mbar_init(FULLB(s), 1);
            mbar_init(EMPTYB(s), CTPB);
        }
        asm volatile("fence.proxy.async.shared::cta;" ::: "memory");
    }
    __syncthreads();

    if (threadIdx.x >= CTPB) {
        // ================= producer warp (warp 8) =================
        if (threadIdx.x == CTPB) {
            const float* posblk = pos + (size_t)e0 * L_TOTAL + l0;
            #pragma unroll
            for (int s = 0; s < NCH; s++) {
                const int st = s & (NSTAGE - 1);
                const int k  = s >> 2;           // fill number of this slot
                if (k > 0)
                    mbar_wait(EMPTYB(st), (uint32_t)((k - 1) & 1));
                mbar_expect_tx(FULLB(st), STAGEB);
                #pragma unroll
                for (int j = 0; j < CH; j++)
                    bulk_cp(sbase + (uint32_t)(st * STAGEB + j * ROWB),
                            posblk + (size_t)(s * CH + j) * L_TOTAL - (j & 3),
                            FULLB(st));
            }
        }
        return;
    }

    // ================= consumer warps (warps 0..7) =================
    const int lbase = l0 + threadIdx.x;

    float p[PD];
    gather_patch(x, lbase, p);

    float* __restrict__ outrow = out + (size_t)e0 * L_TOTAL + lbase;

    #pragma unroll
    for (int cc = 0; cc < NCH; cc++) {
        const int st = cc & (NSTAGE - 1);
        mbar_wait(FULLB(st), (uint32_t)((cc >> 2) & 1));

        #pragma unroll
        for (int j = 0; j < CH; j++) {
            const int e = e0 + cc * CH + j;
            const float4 w0 = cW4[e * 3 + 0];
            const float4 w1 = cW4[e * 3 + 1];
            const float4 w2 = cW4[e * 3 + 2];

            float c0 = fmaf(p[0], w0.x, cB[e]);   // bias folded into chain
            float c1 = p[1] * w0.y;
            c0 = fmaf(p[2],  w0.z, c0);  c1 = fmaf(p[3],  w0.w, c1);
            c0 = fmaf(p[4],  w1.x, c0);  c1 = fmaf(p[5],  w1.y, c1);
            c0 = fmaf(p[6],  w1.z, c0);  c1 = fmaf(p[7],  w1.w, c1);
            c0 = fmaf(p[8],  w2.x, c0);  c1 = fmaf(p[9],  w2.y, c1);
            c0 = fmaf(p[10], w2.z, c0);  c1 = fmaf(p[11], w2.w, c1);

            const float pvv = spv[st * STAGEF + j * ROWF + (j & 3) + threadIdx.x];
            __stcs(outrow + (size_t)(cc * CH + j) * L_TOTAL,
                   (c0 + c1) + pvv);
        }

        mbar_arrive(EMPTYB(st));
    }
}

extern "C" void kernel_launch(void* const* d_in, const int* in_sizes, int n_in,
                              void* d_out, int out_size) {
    const float* x   = (const float*)d_in[0];
    const float* W   = (const float*)d_in[1];
    const float* b   = (const float*)d_in[2];
    const float* pos = (const float*)d_in[3];
    float* out = (float*)d_out;

    cudaMemcpyToSymbolAsync(cW4, W, EMB * PD * sizeof(float), 0,
                            cudaMemcpyDeviceToDevice);
    cudaMemcpyToSymbolAsync(cB, b, EMB * sizeof(float), 0,
                            cudaMemcpyDeviceToDevice);

    dim3 grid((L_TOTAL + CTPB - 1) / CTPB,   // 574 (last = tail path)
              EMB / E_TILE,                  // 12
              1);
    patch_embed_kernel<<<grid, TPB>>>(x, pos, out);
}